// round 8
// baseline (speedup 1.0000x reference)
#include <cuda_runtime.h>
#include <math.h>

#define SEQ   2048
#define LCH   16
#define CE    128
#define CH    256
#define WE    512
#define WH    1024
#define NTAG  128
#define WBLOCKS 128

// ---------------- device scratch ----------------
__device__ float g_WcatT[384 * 1024];     // char [c_Wih | c_Whh]^T : [k][gate_row]
__device__ float g_cbias[1024];           // c_bih + c_bhh
__device__ float g_wbias[4096];           // w_bih + w_bhh
__device__ float g_oWT[1024 * 128];       // out_W^T : [k][tag]
__device__ float g_last[SEQ * CH];        // last char hidden per word
__device__ float g_xw[SEQ * 768];         // concat(word_emb, last_char)
__device__ float g_prew[SEQ * 4096];      // xw @ w_Wih^T + biases
__device__ float g_hs[SEQ * WH];          // word-LSTM hidden history (for out_kernel)
__device__ float g_rec[(size_t)SEQ * WBLOCKS * 16];  // per (step,block) record: h[8], cnt, pad

// ---------------- math helpers ----------------
__device__ __forceinline__ float sigf(float x) {
    return __fdividef(1.0f, 1.0f + __expf(-x));
}
__device__ __forceinline__ float tanhf_(float x) {
    x = fminf(fmaxf(x, -15.0f), 15.0f);
    float t = __expf(2.0f * x);
    return __fdividef(t - 1.0f, t + 1.0f);
}

// ---------------- prep ----------------
__global__ void prep_kernel(const float* __restrict__ cWih, const float* __restrict__ cWhh,
                            const float* __restrict__ cbih, const float* __restrict__ cbhh,
                            const float* __restrict__ wbih, const float* __restrict__ wbhh,
                            const float* __restrict__ outW)
{
    int idx = blockIdx.x * blockDim.x + threadIdx.x;
    int stride = gridDim.x * blockDim.x;
    for (int i = idx; i < 384 * 1024; i += stride) {
        int k = i >> 10, r = i & 1023;
        g_WcatT[i] = (k < CE) ? cWih[r * CE + k] : cWhh[r * CH + (k - CE)];
    }
    for (int i = idx; i < 1024; i += stride) g_cbias[i] = cbih[i] + cbhh[i];
    for (int i = idx; i < 4096; i += stride) g_wbias[i] = wbih[i] + wbhh[i];
    for (int i = idx; i < 1024 * 128; i += stride) {
        int k = i >> 7, j = i & 127;
        g_oWT[i] = outW[j * 1024 + k];
    }
    // reset record counters (slot 8 of each 16-float record) — graph-replay safe
    for (int i = idx; i < SEQ * WBLOCKS; i += stride)
        g_rec[(size_t)i * 16 + 8] = 0.0f;
}

// ---------------- char LSTM ----------------
// 128 blocks x 256 threads, 16 words per block. Thread tid = hidden unit j.
__global__ __launch_bounds__(256, 1) void char_kernel(const int* __restrict__ char_ids,
                                                      const int* __restrict__ char_lens,
                                                      const float* __restrict__ char_emb)
{
    __shared__ __align__(16) float sx[384 * 16];   // xh transposed [k][word]
    __shared__ float sh[16 * CH];                  // h per word
    __shared__ int   scid[16 * LCH];
    __shared__ int   slen[16];

    const int tid = threadIdx.x;
    const int wbase = blockIdx.x * 16;

    scid[tid] = char_ids[wbase * LCH + tid];
    if (tid < 16) slen[tid] = char_lens[wbase + tid];
    for (int i = tid; i < 16 * CH; i += 256) sh[i] = 0.0f;
    __syncthreads();

    const int j = tid;
    float bias[4];
#pragma unroll
    for (int g = 0; g < 4; ++g) bias[g] = g_cbias[g * CH + j];

    float cst[16];
#pragma unroll
    for (int w = 0; w < 16; ++w) cst[w] = 0.0f;

    const int wloc = tid & 15;

    for (int t = 0; t < LCH; ++t) {
        const int cid = scid[wloc * LCH + t];
#pragma unroll
        for (int e = 0; e < 24; ++e) {
            int idx = tid + e * 256;
            int k = idx >> 4;
            sx[idx] = (k < CE) ? char_emb[cid * CE + k]
                               : sh[wloc * CH + (k - CE)];
        }
        __syncthreads();

        float a[4][16];
#pragma unroll
        for (int g = 0; g < 4; ++g)
#pragma unroll
            for (int w = 0; w < 16; ++w) a[g][w] = bias[g];

#pragma unroll 2
        for (int k = 0; k < 384; ++k) {
            const float* wr = &g_WcatT[k * 1024 + j];
            float w0 = __ldg(&wr[0]);
            float w1 = __ldg(&wr[256]);
            float w2 = __ldg(&wr[512]);
            float w3 = __ldg(&wr[768]);
            const float4* bp = (const float4*)&sx[k * 16];
            float4 q0 = bp[0], q1 = bp[1], q2 = bp[2], q3 = bp[3];
            float bb[16] = {q0.x,q0.y,q0.z,q0.w, q1.x,q1.y,q1.z,q1.w,
                            q2.x,q2.y,q2.z,q2.w, q3.x,q3.y,q3.z,q3.w};
#pragma unroll
            for (int w = 0; w < 16; ++w) {
                a[0][w] = fmaf(w0, bb[w], a[0][w]);
                a[1][w] = fmaf(w1, bb[w], a[1][w]);
                a[2][w] = fmaf(w2, bb[w], a[2][w]);
                a[3][w] = fmaf(w3, bb[w], a[3][w]);
            }
        }
        __syncthreads();   // done reading sh for this step

#pragma unroll
        for (int w = 0; w < 16; ++w) {
            float ig = sigf(a[0][w]);
            float fg = sigf(a[1][w]);
            float gg = tanhf_(a[2][w]);
            float og = sigf(a[3][w]);
            float c = fg * cst[w] + ig * gg;
            cst[w] = c;
            float h = og * tanhf_(c);
            sh[w * CH + j] = h;
            if (t == slen[w] - 1) g_last[(wbase + w) * CH + j] = h;
        }
        __syncthreads();
    }
}

// ---------------- xw concat ----------------
__global__ void xw_kernel(const int* __restrict__ word_ids, const float* __restrict__ word_emb)
{
    int t = blockIdx.x;
    int wid = word_ids[t];
    for (int i = threadIdx.x; i < 768; i += blockDim.x)
        g_xw[t * 768 + i] = (i < WE) ? word_emb[(size_t)wid * WE + i]
                                     : g_last[t * CH + (i - WE)];
}

// ---------------- pregemm: g_prew = g_xw @ w_Wih^T + wbias ----------------
__global__ __launch_bounds__(256, 2) void pregemm_kernel(const float* __restrict__ B)
{
    __shared__ float As[16][128];
    __shared__ float Bs[16][128];
    const int tid = threadIdx.x;
    const int tm = tid >> 4, tn = tid & 15;
    const int M0 = blockIdx.x * 128, N0 = blockIdx.y * 128;

    float acc[8][8];
#pragma unroll
    for (int i = 0; i < 8; ++i)
#pragma unroll
        for (int jj = 0; jj < 8; ++jj) acc[i][jj] = 0.0f;

    for (int k0 = 0; k0 < 768; k0 += 16) {
#pragma unroll
        for (int p = 0; p < 2; ++p) {
            int f = tid + p * 256;
            int row = f >> 2, q = f & 3;
            float4 av = *(const float4*)&g_xw[(size_t)(M0 + row) * 768 + k0 + q * 4];
            As[q*4+0][row] = av.x; As[q*4+1][row] = av.y;
            As[q*4+2][row] = av.z; As[q*4+3][row] = av.w;
            float4 bv = *(const float4*)&B[(size_t)(N0 + row) * 768 + k0 + q * 4];
            Bs[q*4+0][row] = bv.x; Bs[q*4+1][row] = bv.y;
            Bs[q*4+2][row] = bv.z; Bs[q*4+3][row] = bv.w;
        }
        __syncthreads();
#pragma unroll
        for (int k = 0; k < 16; ++k) {
            float ar[8], br[8];
            *(float4*)&ar[0] = *(const float4*)&As[k][tm * 8];
            *(float4*)&ar[4] = *(const float4*)&As[k][tm * 8 + 4];
            *(float4*)&br[0] = *(const float4*)&Bs[k][tn * 8];
            *(float4*)&br[4] = *(const float4*)&Bs[k][tn * 8 + 4];
#pragma unroll
            for (int i = 0; i < 8; ++i)
#pragma unroll
                for (int jj = 0; jj < 8; ++jj)
                    acc[i][jj] = fmaf(ar[i], br[jj], acc[i][jj]);
        }
        __syncthreads();
    }

#pragma unroll
    for (int i = 0; i < 8; ++i) {
        int m = M0 + tm * 8 + i;
#pragma unroll
        for (int jj = 0; jj < 8; ++jj) {
            int n = N0 + tn * 8 + jj;
            g_prew[(size_t)m * 4096 + n] = acc[i][jj] + g_wbias[n];
        }
    }
}

// ---------------- word LSTM recurrence: fused h+flag record barrier ----------------
// 128 blocks x 256 threads. Warp = 1 hidden unit; lanes: 4 gates x 8.
// Per step each block publishes one 64B record {h[8], cnt}. Readers poll the 128
// cnts (one per thread, plain volatile loads on distinct lines) and read the h
// payload from the same hot line. Fence discipline identical to R2 (proven).
__global__ __launch_bounds__(256, 1) void word_kernel(const float* __restrict__ whh)
{
    __shared__ __align__(16) float sh[WH];
    const int tid = threadIdx.x;
    const int warp = tid >> 5, lane = tid & 31;
    const int gt = lane >> 3, li = lane & 7;
    const int j = blockIdx.x * 8 + warp;
    const size_t row = (size_t)(gt * WH + j);

    float4 wv[32];
#pragma unroll
    for (int i = 0; i < 32; ++i)
        wv[i] = *(const float4*)&whh[row * WH + li * 4 + 32 * i];

    float c = 0.0f;

    // h_{-1} = 0
    *(float4*)&sh[tid * 4] = make_float4(0.f, 0.f, 0.f, 0.f);
    __syncthreads();

    // prefetch pre-activations for t=0
    float pz0 = __ldg(&g_prew[j]);
    float pz1 = __ldg(&g_prew[j + 1024]);
    float pz2 = __ldg(&g_prew[j + 2048]);
    float pz3 = __ldg(&g_prew[j + 3072]);

    for (int t = 0; t < SEQ; ++t) {
        float a0 = 0.f, a1 = 0.f, a2 = 0.f, a3 = 0.f;
#pragma unroll
        for (int i = 0; i < 32; i += 4) {
            float4 h0 = *(const float4*)&sh[li * 4 + 32 * i];
            float4 h1 = *(const float4*)&sh[li * 4 + 32 * (i + 1)];
            float4 h2 = *(const float4*)&sh[li * 4 + 32 * (i + 2)];
            float4 h3 = *(const float4*)&sh[li * 4 + 32 * (i + 3)];
            float4 w0 = wv[i], w1 = wv[i+1], w2 = wv[i+2], w3 = wv[i+3];
            a0 = fmaf(w0.x, h0.x, a0); a0 = fmaf(w0.y, h0.y, a0);
            a0 = fmaf(w0.z, h0.z, a0); a0 = fmaf(w0.w, h0.w, a0);
            a1 = fmaf(w1.x, h1.x, a1); a1 = fmaf(w1.y, h1.y, a1);
            a1 = fmaf(w1.z, h1.z, a1); a1 = fmaf(w1.w, h1.w, a1);
            a2 = fmaf(w2.x, h2.x, a2); a2 = fmaf(w2.y, h2.y, a2);
            a2 = fmaf(w2.z, h2.z, a2); a2 = fmaf(w2.w, h2.w, a2);
            a3 = fmaf(w3.x, h3.x, a3); a3 = fmaf(w3.y, h3.y, a3);
            a3 = fmaf(w3.z, h3.z, a3); a3 = fmaf(w3.w, h3.w, a3);
        }
        float acc = (a0 + a1) + (a2 + a3);
        acc += __shfl_down_sync(0xffffffffu, acc, 4, 8);
        acc += __shfl_down_sync(0xffffffffu, acc, 2, 8);
        acc += __shfl_down_sync(0xffffffffu, acc, 1, 8);

        float iv = __shfl_sync(0xffffffffu, acc, 0)  + pz0;
        float fv = __shfl_sync(0xffffffffu, acc, 8)  + pz1;
        float gv = __shfl_sync(0xffffffffu, acc, 16) + pz2;
        float ov = __shfl_sync(0xffffffffu, acc, 24) + pz3;

        float ig = sigf(iv), fg = sigf(fv), og = sigf(ov), gg = tanhf_(gv);
        c = fg * c + ig * gg;
        float h = og * tanhf_(c);

        // publish: h into this block's record (+ g_hs for out_kernel, off-path)
        float* rec = &g_rec[((size_t)t * WBLOCKS + blockIdx.x) * 16];
        if (lane == 0) {
            __stcg(&rec[warp], h);
            __stcg(&g_hs[(size_t)t * WH + j], h);
        }
        __syncthreads();                  // all 8 h stores issued before fence
        if (tid == 0) {
            __threadfence();              // drain block's prior global stores
            __stcg(&rec[8], (float)(t + 1));
        }

        if (t != SEQ - 1) {
            // prefetch next step's pre-activations under the wait
            const float* pw = &g_prew[(size_t)(t + 1) * 4096 + j];
            pz0 = __ldg(&pw[0]);
            pz1 = __ldg(&pw[1024]);
            pz2 = __ldg(&pw[2048]);
            pz3 = __ldg(&pw[3072]);

            // one flag per thread, plain volatile loads on distinct lines
            if (tid < WBLOCKS) {
                const float* rb = &g_rec[((size_t)t * WBLOCKS + tid) * 16];
                const float target = (float)(t + 1);
                while (*(volatile const float*)&rb[8] != target) { }
                float4 h0 = __ldcg((const float4*)&rb[0]);
                float4 h1 = __ldcg((const float4*)&rb[4]);
                *(float4*)&sh[tid * 8]     = h0;
                *(float4*)&sh[tid * 8 + 4] = h1;
            }
            __syncthreads();
        }
    }
}

// ---------------- output GEMM + log_softmax ----------------
__global__ __launch_bounds__(128, 2) void out_kernel(const float* __restrict__ out_b,
                                                     float* __restrict__ out)
{
    __shared__ __align__(16) float shh[8 * WH];
    __shared__ float sred[4];
    const int tid = threadIdx.x;
    const int rowbase = blockIdx.x * 8;
    const int wid = tid >> 5, lane = tid & 31;

#pragma unroll
    for (int q = 0; q < 16; ++q) {
        int off = (tid + q * 128) * 4;
        *(float4*)&shh[off] = *(const float4*)&g_hs[(size_t)rowbase * WH + off];
    }
    __syncthreads();

    float acc[8];
#pragma unroll
    for (int r = 0; r < 8; ++r) acc[r] = 0.0f;

#pragma unroll 4
    for (int k = 0; k < WH; ++k) {
        float wv = __ldg(&g_oWT[k * NTAG + tid]);
#pragma unroll
        for (int r = 0; r < 8; ++r)
            acc[r] = fmaf(wv, shh[r * WH + k], acc[r]);
    }

    const float b = out_b[tid];
    for (int r = 0; r < 8; ++r) {
        float v = acc[r] + b;
        float m = v;
#pragma unroll
        for (int o = 16; o >= 1; o >>= 1) m = fmaxf(m, __shfl_xor_sync(0xffffffffu, m, o));
        if (lane == 0) sred[wid] = m;
        __syncthreads();
        m = fmaxf(fmaxf(sred[0], sred[1]), fmaxf(sred[2], sred[3]));
        __syncthreads();
        float e = __expf(v - m);
        float s = e;
#pragma unroll
        for (int o = 16; o >= 1; o >>= 1) s += __shfl_xor_sync(0xffffffffu, s, o);
        if (lane == 0) sred[wid] = s;
        __syncthreads();
        s = sred[0] + sred[1] + sred[2] + sred[3];
        __syncthreads();
        out[(size_t)(rowbase + r) * NTAG + tid] = v - m - __logf(s);
    }
}

// ---------------- launch ----------------
extern "C" void kernel_launch(void* const* d_in, const int* in_sizes, int n_in,
                              void* d_out, int out_size)
{
    const int*   word_ids  = (const int*)d_in[0];
    const int*   char_ids  = (const int*)d_in[1];
    const int*   char_lens = (const int*)d_in[2];
    const float* char_emb  = (const float*)d_in[3];
    const float* word_emb  = (const float*)d_in[4];
    const float* c_Wih     = (const float*)d_in[5];
    const float* c_Whh     = (const float*)d_in[6];
    const float* c_bih     = (const float*)d_in[7];
    const float* c_bhh     = (const float*)d_in[8];
    const float* w_Wih     = (const float*)d_in[9];
    const float* w_Whh     = (const float*)d_in[10];
    const float* w_bih     = (const float*)d_in[11];
    const float* w_bhh     = (const float*)d_in[12];
    const float* out_W     = (const float*)d_in[13];
    const float* out_b     = (const float*)d_in[14];
    float* out = (float*)d_out;

    prep_kernel<<<512, 256>>>(c_Wih, c_Whh, c_bih, c_bhh, w_bih, w_bhh, out_W);
    char_kernel<<<128, 256>>>(char_ids, char_lens, char_emb);
    xw_kernel<<<SEQ, 256>>>(word_ids, word_emb);
    pregemm_kernel<<<dim3(16, 32), 256>>>(w_Wih);
    word_kernel<<<WBLOCKS, 256>>>(w_Whh);
    out_kernel<<<256, 128>>>(out_b, out);
}

// round 9
// speedup vs baseline: 1.7492x; 1.7492x over previous
#include <cuda_runtime.h>
#include <math.h>

#define SEQ   2048
#define LCH   16
#define CE    128
#define CH    256
#define WE    512
#define WH    1024
#define NTAG  128
#define WBLOCKS 128

// ---------------- device scratch ----------------
__device__ float g_WcatT[384 * 1024];     // char [c_Wih | c_Whh]^T : [k][gate_row]
__device__ float g_cbias[1024];           // c_bih + c_bhh
__device__ float g_wbias[4096];           // w_bih + w_bhh
__device__ float g_oWT[1024 * 128];       // out_W^T : [k][tag]
__device__ float g_last[SEQ * CH];        // last char hidden per word
__device__ float g_prew[SEQ * 4096];      // x @ w_Wih^T + biases
__device__ float g_hs[SEQ * WH];          // word-LSTM hidden history
__device__ unsigned int g_bar;            // grid barrier counter

// ---------------- sync + math helpers ----------------
__device__ __forceinline__ void red_release_add(unsigned* p, unsigned v) {
    asm volatile("red.release.gpu.global.add.u32 [%0],%1;" :: "l"(p), "r"(v) : "memory");
}
__device__ __forceinline__ unsigned ld_acq(const unsigned* p) {
    unsigned v; asm volatile("ld.acquire.gpu.global.u32 %0,[%1];" : "=r"(v) : "l"(p) : "memory"); return v;
}
__device__ __forceinline__ float sigf(float x) {
    return __fdividef(1.0f, 1.0f + __expf(-x));
}
__device__ __forceinline__ float tanhf_(float x) {
    x = fminf(fmaxf(x, -15.0f), 15.0f);
    float t = __expf(2.0f * x);
    return __fdividef(t - 1.0f, t + 1.0f);
}

// ---------------- prep ----------------
__global__ void prep_kernel(const float* __restrict__ cWih, const float* __restrict__ cWhh,
                            const float* __restrict__ cbih, const float* __restrict__ cbhh,
                            const float* __restrict__ wbih, const float* __restrict__ wbhh,
                            const float* __restrict__ outW)
{
    int idx = blockIdx.x * blockDim.x + threadIdx.x;
    int stride = gridDim.x * blockDim.x;
    for (int i = idx; i < 384 * 1024; i += stride) {
        int k = i >> 10, r = i & 1023;
        g_WcatT[i] = (k < CE) ? cWih[r * CE + k] : cWhh[r * CH + (k - CE)];
    }
    for (int i = idx; i < 1024; i += stride) g_cbias[i] = cbih[i] + cbhh[i];
    for (int i = idx; i < 4096; i += stride) g_wbias[i] = wbih[i] + wbhh[i];
    for (int i = idx; i < 1024 * 128; i += stride) {
        int k = i >> 7, j = i & 127;
        g_oWT[i] = outW[j * 1024 + k];
    }
    if (idx == 0) g_bar = 0u;   // graph-replay determinism
}

// ---------------- char LSTM ----------------
// 128 blocks x 256 threads, 16 words per block. Thread tid = hidden unit j.
__global__ __launch_bounds__(256, 1) void char_kernel(const int* __restrict__ char_ids,
                                                      const int* __restrict__ char_lens,
                                                      const float* __restrict__ char_emb)
{
    __shared__ __align__(16) float sx[384 * 16];   // xh transposed [k][word]
    __shared__ float sh[16 * CH];                  // h per word
    __shared__ int   scid[16 * LCH];
    __shared__ int   slen[16];

    const int tid = threadIdx.x;
    const int wbase = blockIdx.x * 16;

    scid[tid] = char_ids[wbase * LCH + tid];
    if (tid < 16) slen[tid] = char_lens[wbase + tid];
    for (int i = tid; i < 16 * CH; i += 256) sh[i] = 0.0f;
    __syncthreads();

    const int j = tid;
    float bias[4];
#pragma unroll
    for (int g = 0; g < 4; ++g) bias[g] = g_cbias[g * CH + j];

    float cst[16];
#pragma unroll
    for (int w = 0; w < 16; ++w) cst[w] = 0.0f;

    const int wloc = tid & 15;

    for (int t = 0; t < LCH; ++t) {
        const int cid = scid[wloc * LCH + t];
#pragma unroll
        for (int e = 0; e < 24; ++e) {
            int idx = tid + e * 256;
            int k = idx >> 4;
            sx[idx] = (k < CE) ? char_emb[cid * CE + k]
                               : sh[wloc * CH + (k - CE)];
        }
        __syncthreads();

        float a[4][16];
#pragma unroll
        for (int g = 0; g < 4; ++g)
#pragma unroll
            for (int w = 0; w < 16; ++w) a[g][w] = bias[g];

#pragma unroll 2
        for (int k = 0; k < 384; ++k) {
            const float* wr = &g_WcatT[k * 1024 + j];
            float w0 = __ldg(&wr[0]);
            float w1 = __ldg(&wr[256]);
            float w2 = __ldg(&wr[512]);
            float w3 = __ldg(&wr[768]);
            const float4* bp = (const float4*)&sx[k * 16];
            float4 q0 = bp[0], q1 = bp[1], q2 = bp[2], q3 = bp[3];
            float bb[16] = {q0.x,q0.y,q0.z,q0.w, q1.x,q1.y,q1.z,q1.w,
                            q2.x,q2.y,q2.z,q2.w, q3.x,q3.y,q3.z,q3.w};
#pragma unroll
            for (int w = 0; w < 16; ++w) {
                a[0][w] = fmaf(w0, bb[w], a[0][w]);
                a[1][w] = fmaf(w1, bb[w], a[1][w]);
                a[2][w] = fmaf(w2, bb[w], a[2][w]);
                a[3][w] = fmaf(w3, bb[w], a[3][w]);
            }
        }
        __syncthreads();   // done reading sh for this step

#pragma unroll
        for (int w = 0; w < 16; ++w) {
            float ig = sigf(a[0][w]);
            float fg = sigf(a[1][w]);
            float gg = tanhf_(a[2][w]);
            float og = sigf(a[3][w]);
            float c = fg * cst[w] + ig * gg;
            cst[w] = c;
            float h = og * tanhf_(c);
            sh[w * CH + j] = h;
            if (t == slen[w] - 1) g_last[(wbase + w) * CH + j] = h;
        }
        __syncthreads();
    }
}

// ---------------- pregemm (xw concat fused into A-tile load) ----------------
// g_prew[2048,4096] = concat(word_emb[word_ids], g_last) @ w_Wih^T + wbias
__global__ __launch_bounds__(256, 2) void pregemm_kernel(const float* __restrict__ B,
                                                         const int* __restrict__ word_ids,
                                                         const float* __restrict__ word_emb)
{
    __shared__ float As[16][128];
    __shared__ float Bs[16][128];
    __shared__ int   swid[128];
    const int tid = threadIdx.x;
    const int tm = tid >> 4, tn = tid & 15;
    const int M0 = blockIdx.x * 128, N0 = blockIdx.y * 128;

    if (tid < 128) swid[tid] = word_ids[M0 + tid];
    __syncthreads();

    float acc[8][8];
#pragma unroll
    for (int i = 0; i < 8; ++i)
#pragma unroll
        for (int jj = 0; jj < 8; ++jj) acc[i][jj] = 0.0f;

    for (int k0 = 0; k0 < 768; k0 += 16) {
#pragma unroll
        for (int p = 0; p < 2; ++p) {
            int f = tid + p * 256;
            int row = f >> 2, q = f & 3;
            int col = k0 + q * 4;
            float4 av;
            if (col < WE) av = *(const float4*)&word_emb[(size_t)swid[row] * WE + col];
            else          av = *(const float4*)&g_last[(size_t)(M0 + row) * CH + (col - WE)];
            As[q*4+0][row] = av.x; As[q*4+1][row] = av.y;
            As[q*4+2][row] = av.z; As[q*4+3][row] = av.w;
            float4 bv = *(const float4*)&B[(size_t)(N0 + row) * 768 + col];
            Bs[q*4+0][row] = bv.x; Bs[q*4+1][row] = bv.y;
            Bs[q*4+2][row] = bv.z; Bs[q*4+3][row] = bv.w;
        }
        __syncthreads();
#pragma unroll
        for (int k = 0; k < 16; ++k) {
            float ar[8], br[8];
            *(float4*)&ar[0] = *(const float4*)&As[k][tm * 8];
            *(float4*)&ar[4] = *(const float4*)&As[k][tm * 8 + 4];
            *(float4*)&br[0] = *(const float4*)&Bs[k][tn * 8];
            *(float4*)&br[4] = *(const float4*)&Bs[k][tn * 8 + 4];
#pragma unroll
            for (int i = 0; i < 8; ++i)
#pragma unroll
                for (int jj = 0; jj < 8; ++jj)
                    acc[i][jj] = fmaf(ar[i], br[jj], acc[i][jj]);
        }
        __syncthreads();
    }

#pragma unroll
    for (int i = 0; i < 8; ++i) {
        int m = M0 + tm * 8 + i;
#pragma unroll
        for (int jj = 0; jj < 8; ++jj) {
            int n = N0 + tn * 8 + jj;
            g_prew[(size_t)m * 4096 + n] = acc[i][jj] + g_wbias[n];
        }
    }
}

// ---------------- word LSTM recurrence: R2 barrier + backoff + release-red ------
// 128 blocks x 256 threads. Warp = 1 hidden unit; lanes: 4 gates x 8.
__global__ __launch_bounds__(256, 1) void word_kernel(const float* __restrict__ whh)
{
    __shared__ __align__(16) float sh[WH];
    const int tid = threadIdx.x;
    const int warp = tid >> 5, lane = tid & 31;
    const int gt = lane >> 3, li = lane & 7;
    const int j = blockIdx.x * 8 + warp;
    const size_t row = (size_t)(gt * WH + j);

    float4 wv[32];
#pragma unroll
    for (int i = 0; i < 32; ++i)
        wv[i] = *(const float4*)&whh[row * WH + li * 4 + 32 * i];

    float c = 0.0f;
    unsigned goal = 0;

    // prefetch pre-activations for t=0
    float pz0 = __ldg(&g_prew[j]);
    float pz1 = __ldg(&g_prew[j + 1024]);
    float pz2 = __ldg(&g_prew[j + 2048]);
    float pz3 = __ldg(&g_prew[j + 3072]);

    for (int t = 0; t < SEQ; ++t) {
        // stage h_{t-1}
        float4 hv4;
        if (t == 0) hv4 = make_float4(0.f, 0.f, 0.f, 0.f);
        else        hv4 = __ldcg((const float4*)&g_hs[(size_t)(t - 1) * WH + tid * 4]);
        *(float4*)&sh[tid * 4] = hv4;
        __syncthreads();

        float a0 = 0.f, a1 = 0.f, a2 = 0.f, a3 = 0.f;
#pragma unroll
        for (int i = 0; i < 32; i += 4) {
            float4 h0 = *(const float4*)&sh[li * 4 + 32 * i];
            float4 h1 = *(const float4*)&sh[li * 4 + 32 * (i + 1)];
            float4 h2 = *(const float4*)&sh[li * 4 + 32 * (i + 2)];
            float4 h3 = *(const float4*)&sh[li * 4 + 32 * (i + 3)];
            float4 w0 = wv[i], w1 = wv[i+1], w2 = wv[i+2], w3 = wv[i+3];
            a0 = fmaf(w0.x, h0.x, a0); a0 = fmaf(w0.y, h0.y, a0);
            a0 = fmaf(w0.z, h0.z, a0); a0 = fmaf(w0.w, h0.w, a0);
            a1 = fmaf(w1.x, h1.x, a1); a1 = fmaf(w1.y, h1.y, a1);
            a1 = fmaf(w1.z, h1.z, a1); a1 = fmaf(w1.w, h1.w, a1);
            a2 = fmaf(w2.x, h2.x, a2); a2 = fmaf(w2.y, h2.y, a2);
            a2 = fmaf(w2.z, h2.z, a2); a2 = fmaf(w2.w, h2.w, a2);
            a3 = fmaf(w3.x, h3.x, a3); a3 = fmaf(w3.y, h3.y, a3);
            a3 = fmaf(w3.z, h3.z, a3); a3 = fmaf(w3.w, h3.w, a3);
        }
        float acc = (a0 + a1) + (a2 + a3);
        acc += __shfl_down_sync(0xffffffffu, acc, 4, 8);
        acc += __shfl_down_sync(0xffffffffu, acc, 2, 8);
        acc += __shfl_down_sync(0xffffffffu, acc, 1, 8);

        float iv = __shfl_sync(0xffffffffu, acc, 0)  + pz0;
        float fv = __shfl_sync(0xffffffffu, acc, 8)  + pz1;
        float gv = __shfl_sync(0xffffffffu, acc, 16) + pz2;
        float ov = __shfl_sync(0xffffffffu, acc, 24) + pz3;

        float ig = sigf(iv), fg = sigf(fv), og = sigf(ov), gg = tanhf_(gv);
        c = fg * c + ig * gg;
        float h = og * tanhf_(c);

        if (lane == 0) __stcg(&g_hs[(size_t)t * WH + j], h);
        __syncthreads();                 // all 8 h stores happen-before tid0's release

        if (t != SEQ - 1) {
            if (tid == 0) red_release_add(&g_bar, 1u);   // cumulative release

            // prefetch next step's pre-activations under the wait
            const float* pw = &g_prew[(size_t)(t + 1) * 4096 + j];
            pz0 = __ldg(&pw[0]);
            pz1 = __ldg(&pw[1024]);
            pz2 = __ldg(&pw[2048]);
            pz3 = __ldg(&pw[3072]);

            goal += WBLOCKS;
            if (tid == 0) {
                for (;;) {
                    unsigned v = ld_acq(&g_bar);
                    if (v >= goal) break;
                    // ~64-cyc backoff: dependent integer chain (kept alive via asm sink)
                    unsigned x = v + 0x9e3779b9u;
#pragma unroll
                    for (int z = 0; z < 16; ++z) x = x * 1664525u + 1013904223u;
                    asm volatile("" :: "r"(x));
                }
            }
            __syncthreads();
        }
    }
}

// ---------------- output GEMM + log_softmax ----------------
__global__ __launch_bounds__(128, 2) void out_kernel(const float* __restrict__ out_b,
                                                     float* __restrict__ out)
{
    __shared__ __align__(16) float shh[8 * WH];
    __shared__ float sred[4];
    const int tid = threadIdx.x;
    const int rowbase = blockIdx.x * 8;
    const int wid = tid >> 5, lane = tid & 31;

#pragma unroll
    for (int q = 0; q < 16; ++q) {
        int off = (tid + q * 128) * 4;
        *(float4*)&shh[off] = *(const float4*)&g_hs[(size_t)rowbase * WH + off];
    }
    __syncthreads();

    float acc[8];
#pragma unroll
    for (int r = 0; r < 8; ++r) acc[r] = 0.0f;

#pragma unroll 4
    for (int k = 0; k < WH; ++k) {
        float wv = __ldg(&g_oWT[k * NTAG + tid]);
#pragma unroll
        for (int r = 0; r < 8; ++r)
            acc[r] = fmaf(wv, shh[r * WH + k], acc[r]);
    }

    const float b = out_b[tid];
    for (int r = 0; r < 8; ++r) {
        float v = acc[r] + b;
        float m = v;
#pragma unroll
        for (int o = 16; o >= 1; o >>= 1) m = fmaxf(m, __shfl_xor_sync(0xffffffffu, m, o));
        if (lane == 0) sred[wid] = m;
        __syncthreads();
        m = fmaxf(fmaxf(sred[0], sred[1]), fmaxf(sred[2], sred[3]));
        __syncthreads();
        float e = __expf(v - m);
        float s = e;
#pragma unroll
        for (int o = 16; o >= 1; o >>= 1) s += __shfl_xor_sync(0xffffffffu, s, o);
        if (lane == 0) sred[wid] = s;
        __syncthreads();
        s = sred[0] + sred[1] + sred[2] + sred[3];
        __syncthreads();
        out[(size_t)(rowbase + r) * NTAG + tid] = v - m - __logf(s);
    }
}

// ---------------- launch ----------------
extern "C" void kernel_launch(void* const* d_in, const int* in_sizes, int n_in,
                              void* d_out, int out_size)
{
    const int*   word_ids  = (const int*)d_in[0];
    const int*   char_ids  = (const int*)d_in[1];
    const int*   char_lens = (const int*)d_in[2];
    const float* char_emb  = (const float*)d_in[3];
    const float* word_emb  = (const float*)d_in[4];
    const float* c_Wih     = (const float*)d_in[5];
    const float* c_Whh     = (const float*)d_in[6];
    const float* c_bih     = (const float*)d_in[7];
    const float* c_bhh     = (const float*)d_in[8];
    const float* w_Wih     = (const float*)d_in[9];
    const float* w_Whh     = (const float*)d_in[10];
    const float* w_bih     = (const float*)d_in[11];
    const float* w_bhh     = (const float*)d_in[12];
    const float* out_W     = (const float*)d_in[13];
    const float* out_b     = (const float*)d_in[14];
    float* out = (float*)d_out;

    prep_kernel<<<512, 256>>>(c_Wih, c_Whh, c_bih, c_bhh, w_bih, w_bhh, out_W);
    char_kernel<<<128, 256>>>(char_ids, char_lens, char_emb);
    pregemm_kernel<<<dim3(16, 32), 256>>>(w_Wih, word_ids, word_emb);
    word_kernel<<<WBLOCKS, 256>>>(w_Whh);
    out_kernel<<<256, 128>>>(out_b, out);
}

// round 11
// speedup vs baseline: 1.7557x; 1.0037x over previous
#include <cuda_runtime.h>
#include <math.h>

#define SEQ   2048
#define LCH   16
#define CE    128
#define CH    256
#define WE    512
#define WH    1024
#define NTAG  128
#define WBLOCKS 128

// ---------------- device scratch ----------------
__device__ float g_WcatT[384 * 1024];     // char [c_Wih | c_Whh]^T : [k][gate_row]
__device__ float g_cbias[1024];           // c_bih + c_bhh
__device__ float g_wbias[4096];           // w_bih + w_bhh
__device__ float g_oWT[1024 * 128];       // out_W^T : [k][tag]
__device__ float g_last[SEQ * CH];        // last char hidden per word
__device__ float g_prew[SEQ * 4096];      // x @ w_Wih^T + biases
__device__ float g_hs[SEQ * WH];          // word-LSTM hidden history
__device__ unsigned int g_bar;            // grid barrier counter

// ---------------- sync + math helpers ----------------
__device__ __forceinline__ void red_release_add(unsigned* p, unsigned v) {
    asm volatile("red.release.gpu.global.add.u32 [%0],%1;" :: "l"(p), "r"(v) : "memory");
}
__device__ __forceinline__ unsigned ld_acq(const unsigned* p) {
    unsigned v; asm volatile("ld.acquire.gpu.global.u32 %0,[%1];" : "=r"(v) : "l"(p) : "memory"); return v;
}
__device__ __forceinline__ float sigf(float x) {
    return __fdividef(1.0f, 1.0f + __expf(-x));
}
__device__ __forceinline__ float tanhf_(float x) {
    x = fminf(fmaxf(x, -15.0f), 15.0f);
    float t = __expf(2.0f * x);
    return __fdividef(t - 1.0f, t + 1.0f);
}

// ---------------- prep ----------------
__global__ void prep_kernel(const float* __restrict__ cWih, const float* __restrict__ cWhh,
                            const float* __restrict__ cbih, const float* __restrict__ cbhh,
                            const float* __restrict__ wbih, const float* __restrict__ wbhh,
                            const float* __restrict__ outW)
{
    int idx = blockIdx.x * blockDim.x + threadIdx.x;
    int stride = gridDim.x * blockDim.x;
    for (int i = idx; i < 384 * 1024; i += stride) {
        int k = i >> 10, r = i & 1023;
        g_WcatT[i] = (k < CE) ? cWih[r * CE + k] : cWhh[r * CH + (k - CE)];
    }
    for (int i = idx; i < 1024; i += stride) g_cbias[i] = cbih[i] + cbhh[i];
    for (int i = idx; i < 4096; i += stride) g_wbias[i] = wbih[i] + wbhh[i];
    for (int i = idx; i < 1024 * 128; i += stride) {
        int k = i >> 7, j = i & 127;
        g_oWT[i] = outW[j * 1024 + k];
    }
    if (idx == 0) g_bar = 0u;   // graph-replay determinism
}

// ---------------- char LSTM ----------------
// 128 blocks x 256 threads, 16 words per block. Thread tid = hidden unit j.
__global__ __launch_bounds__(256, 1) void char_kernel(const int* __restrict__ char_ids,
                                                      const int* __restrict__ char_lens,
                                                      const float* __restrict__ char_emb)
{
    __shared__ __align__(16) float sx[384 * 16];   // xh transposed [k][word]
    __shared__ float sh[16 * CH];                  // h per word
    __shared__ int   scid[16 * LCH];
    __shared__ int   slen[16];

    const int tid = threadIdx.x;
    const int wbase = blockIdx.x * 16;

    scid[tid] = char_ids[wbase * LCH + tid];
    if (tid < 16) slen[tid] = char_lens[wbase + tid];
    for (int i = tid; i < 16 * CH; i += 256) sh[i] = 0.0f;
    __syncthreads();

    const int j = tid;
    float bias[4];
#pragma unroll
    for (int g = 0; g < 4; ++g) bias[g] = g_cbias[g * CH + j];

    float cst[16];
#pragma unroll
    for (int w = 0; w < 16; ++w) cst[w] = 0.0f;

    const int wloc = tid & 15;

    for (int t = 0; t < LCH; ++t) {
        const int cid = scid[wloc * LCH + t];
#pragma unroll
        for (int e = 0; e < 24; ++e) {
            int idx = tid + e * 256;
            int k = idx >> 4;
            sx[idx] = (k < CE) ? char_emb[cid * CE + k]
                               : sh[wloc * CH + (k - CE)];
        }
        __syncthreads();

        float a[4][16];
#pragma unroll
        for (int g = 0; g < 4; ++g)
#pragma unroll
            for (int w = 0; w < 16; ++w) a[g][w] = bias[g];

#pragma unroll 2
        for (int k = 0; k < 384; ++k) {
            const float* wr = &g_WcatT[k * 1024 + j];
            float w0 = __ldg(&wr[0]);
            float w1 = __ldg(&wr[256]);
            float w2 = __ldg(&wr[512]);
            float w3 = __ldg(&wr[768]);
            const float4* bp = (const float4*)&sx[k * 16];
            float4 q0 = bp[0], q1 = bp[1], q2 = bp[2], q3 = bp[3];
            float bb[16] = {q0.x,q0.y,q0.z,q0.w, q1.x,q1.y,q1.z,q1.w,
                            q2.x,q2.y,q2.z,q2.w, q3.x,q3.y,q3.z,q3.w};
#pragma unroll
            for (int w = 0; w < 16; ++w) {
                a[0][w] = fmaf(w0, bb[w], a[0][w]);
                a[1][w] = fmaf(w1, bb[w], a[1][w]);
                a[2][w] = fmaf(w2, bb[w], a[2][w]);
                a[3][w] = fmaf(w3, bb[w], a[3][w]);
            }
        }
        __syncthreads();   // done reading sh for this step

#pragma unroll
        for (int w = 0; w < 16; ++w) {
            float ig = sigf(a[0][w]);
            float fg = sigf(a[1][w]);
            float gg = tanhf_(a[2][w]);
            float og = sigf(a[3][w]);
            float c = fg * cst[w] + ig * gg;
            cst[w] = c;
            float h = og * tanhf_(c);
            sh[w * CH + j] = h;
            if (t == slen[w] - 1) g_last[(wbase + w) * CH + j] = h;
        }
        __syncthreads();
    }
}

// ---------------- pregemm (xw concat fused into A-tile load) ----------------
// g_prew[2048,4096] = concat(word_emb[word_ids], g_last) @ w_Wih^T + wbias
__global__ __launch_bounds__(256, 2) void pregemm_kernel(const float* __restrict__ B,
                                                         const int* __restrict__ word_ids,
                                                         const float* __restrict__ word_emb)
{
    __shared__ float As[16][128];
    __shared__ float Bs[16][128];
    __shared__ int   swid[128];
    const int tid = threadIdx.x;
    const int tm = tid >> 4, tn = tid & 15;
    const int M0 = blockIdx.x * 128, N0 = blockIdx.y * 128;

    if (tid < 128) swid[tid] = word_ids[M0 + tid];
    __syncthreads();

    float acc[8][8];
#pragma unroll
    for (int i = 0; i < 8; ++i)
#pragma unroll
        for (int jj = 0; jj < 8; ++jj) acc[i][jj] = 0.0f;

    for (int k0 = 0; k0 < 768; k0 += 16) {
#pragma unroll
        for (int p = 0; p < 2; ++p) {
            int f = tid + p * 256;
            int row = f >> 2, q = f & 3;
            int col = k0 + q * 4;
            float4 av;
            if (col < WE) av = *(const float4*)&word_emb[(size_t)swid[row] * WE + col];
            else          av = *(const float4*)&g_last[(size_t)(M0 + row) * CH + (col - WE)];
            As[q*4+0][row] = av.x; As[q*4+1][row] = av.y;
            As[q*4+2][row] = av.z; As[q*4+3][row] = av.w;
            float4 bv = *(const float4*)&B[(size_t)(N0 + row) * 768 + col];
            Bs[q*4+0][row] = bv.x; Bs[q*4+1][row] = bv.y;
            Bs[q*4+2][row] = bv.z; Bs[q*4+3][row] = bv.w;
        }
        __syncthreads();
#pragma unroll
        for (int k = 0; k < 16; ++k) {
            float ar[8], br[8];
            *(float4*)&ar[0] = *(const float4*)&As[k][tm * 8];
            *(float4*)&ar[4] = *(const float4*)&As[k][tm * 8 + 4];
            *(float4*)&br[0] = *(const float4*)&Bs[k][tn * 8];
            *(float4*)&br[4] = *(const float4*)&Bs[k][tn * 8 + 4];
#pragma unroll
            for (int i = 0; i < 8; ++i)
#pragma unroll
                for (int jj = 0; jj < 8; ++jj)
                    acc[i][jj] = fmaf(ar[i], br[jj], acc[i][jj]);
        }
        __syncthreads();
    }

#pragma unroll
    for (int i = 0; i < 8; ++i) {
        int m = M0 + tm * 8 + i;
#pragma unroll
        for (int jj = 0; jj < 8; ++jj) {
            int n = N0 + tn * 8 + jj;
            g_prew[(size_t)m * 4096 + n] = acc[i][jj] + g_wbias[n];
        }
    }
}

// ---------------- word LSTM recurrence ----------------
// 128 blocks x 256 threads. Warp = 1 hidden unit; lanes: 4 gates x 8.
// Whh register-resident. Single-counter barrier, tid0 tight poll.
__global__ __launch_bounds__(256, 1) void word_kernel(const float* __restrict__ whh)
{
    __shared__ __align__(16) float sh[WH];
    const int tid = threadIdx.x;
    const int warp = tid >> 5, lane = tid & 31;
    const int gt = lane >> 3, li = lane & 7;
    const int j = blockIdx.x * 8 + warp;
    const size_t row = (size_t)(gt * WH + j);

    float4 wv[32];
#pragma unroll
    for (int i = 0; i < 32; ++i)
        wv[i] = *(const float4*)&whh[row * WH + li * 4 + 32 * i];

    float c = 0.0f;
    unsigned goal = 0;

    // prefetch pre-activations for t=0
    float pz0 = __ldg(&g_prew[j]);
    float pz1 = __ldg(&g_prew[j + 1024]);
    float pz2 = __ldg(&g_prew[j + 2048]);
    float pz3 = __ldg(&g_prew[j + 3072]);

    for (int t = 0; t < SEQ; ++t) {
        // stage h_{t-1}
        float4 hv4;
        if (t == 0) hv4 = make_float4(0.f, 0.f, 0.f, 0.f);
        else        hv4 = __ldcg((const float4*)&g_hs[(size_t)(t - 1) * WH + tid * 4]);
        *(float4*)&sh[tid * 4] = hv4;
        __syncthreads();

        float a0 = 0.f, a1 = 0.f, a2 = 0.f, a3 = 0.f;
#pragma unroll
        for (int i = 0; i < 32; i += 4) {
            float4 h0 = *(const float4*)&sh[li * 4 + 32 * i];
            float4 h1 = *(const float4*)&sh[li * 4 + 32 * (i + 1)];
            float4 h2 = *(const float4*)&sh[li * 4 + 32 * (i + 2)];
            float4 h3 = *(const float4*)&sh[li * 4 + 32 * (i + 3)];
            float4 w0 = wv[i], w1 = wv[i+1], w2 = wv[i+2], w3 = wv[i+3];
            a0 = fmaf(w0.x, h0.x, a0); a0 = fmaf(w0.y, h0.y, a0);
            a0 = fmaf(w0.z, h0.z, a0); a0 = fmaf(w0.w, h0.w, a0);
            a1 = fmaf(w1.x, h1.x, a1); a1 = fmaf(w1.y, h1.y, a1);
            a1 = fmaf(w1.z, h1.z, a1); a1 = fmaf(w1.w, h1.w, a1);
            a2 = fmaf(w2.x, h2.x, a2); a2 = fmaf(w2.y, h2.y, a2);
            a2 = fmaf(w2.z, h2.z, a2); a2 = fmaf(w2.w, h2.w, a2);
            a3 = fmaf(w3.x, h3.x, a3); a3 = fmaf(w3.y, h3.y, a3);
            a3 = fmaf(w3.z, h3.z, a3); a3 = fmaf(w3.w, h3.w, a3);
        }
        float acc = (a0 + a1) + (a2 + a3);
        acc += __shfl_down_sync(0xffffffffu, acc, 4, 8);
        acc += __shfl_down_sync(0xffffffffu, acc, 2, 8);
        acc += __shfl_down_sync(0xffffffffu, acc, 1, 8);

        // gather the 3 other gate sums to lane 0 (c/h only consumed on lane 0;
        // off-lane values are benign garbage — tanhf_ clamps, sigf saturates)
        float fvp = __shfl_sync(0xffffffffu, acc, 8);
        float gvp = __shfl_sync(0xffffffffu, acc, 16);
        float ovp = __shfl_sync(0xffffffffu, acc, 24);

        float iv = acc + pz0;        // valid on lane 0
        float fv = fvp + pz1;
        float gv = gvp + pz2;
        float ov = ovp + pz3;

        float ig = sigf(iv), fg = sigf(fv), og = sigf(ov), gg = tanhf_(gv);
        c = fg * c + ig * gg;
        float h = og * tanhf_(c);

        if (lane == 0) __stcg(&g_hs[(size_t)t * WH + j], h);
        __syncthreads();                 // all 8 h stores happen-before tid0's release

        if (t != SEQ - 1) {
            if (tid == 0) red_release_add(&g_bar, 1u);   // cumulative release

            // prefetch next step's pre-activations under the wait
            const float* pw = &g_prew[(size_t)(t + 1) * 4096 + j];
            pz0 = __ldg(&pw[0]);
            pz1 = __ldg(&pw[1024]);
            pz2 = __ldg(&pw[2048]);
            pz3 = __ldg(&pw[3072]);

            goal += WBLOCKS;
            if (tid == 0) {
                while (ld_acq(&g_bar) < goal) { }       // tight poll, RTT-paced
            }
            __syncthreads();
        }
    }
}

// ---------------- output GEMM + log_softmax ----------------
__global__ __launch_bounds__(128, 2) void out_kernel(const float* __restrict__ out_b,
                                                     float* __restrict__ out)
{
    __shared__ __align__(16) float shh[8 * WH];
    __shared__ float sred[4];
    const int tid = threadIdx.x;
    const int rowbase = blockIdx.x * 8;
    const int wid = tid >> 5, lane = tid & 31;

#pragma unroll
    for (int q = 0; q < 16; ++q) {
        int off = (tid + q * 128) * 4;
        *(float4*)&shh[off] = *(const float4*)&g_hs[(size_t)rowbase * WH + off];
    }
    __syncthreads();

    float acc[8];
#pragma unroll
    for (int r = 0; r < 8; ++r) acc[r] = 0.0f;

#pragma unroll 4
    for (int k = 0; k < WH; ++k) {
        float wv = __ldg(&g_oWT[k * NTAG + tid]);
#pragma unroll
        for (int r = 0; r < 8; ++r)
            acc[r] = fmaf(wv, shh[r * WH + k], acc[r]);
    }

    const float b = out_b[tid];
    for (int r = 0; r < 8; ++r) {
        float v = acc[r] + b;
        float m = v;
#pragma unroll
        for (int o = 16; o >= 1; o >>= 1) m = fmaxf(m, __shfl_xor_sync(0xffffffffu, m, o));
        if (lane == 0) sred[wid] = m;
        __syncthreads();
        m = fmaxf(fmaxf(sred[0], sred[1]), fmaxf(sred[2], sred[3]));
        __syncthreads();
        float e = __expf(v - m);
        float s = e;
#pragma unroll
        for (int o = 16; o >= 1; o >>= 1) s += __shfl_xor_sync(0xffffffffu, s, o);
        if (lane == 0) sred[wid] = s;
        __syncthreads();
        s = sred[0] + sred[1] + sred[2] + sred[3];
        __syncthreads();
        out[(size_t)(rowbase + r) * NTAG + tid] = v - m - __logf(s);
    }
}

// ---------------- launch ----------------
extern "C" void kernel_launch(void* const* d_in, const int* in_sizes, int n_in,
                              void* d_out, int out_size)
{
    const int*   word_ids  = (const int*)d_in[0];
    const int*   char_ids  = (const int*)d_in[1];
    const int*   char_lens = (const int*)d_in[2];
    const float* char_emb  = (const float*)d_in[3];
    const float* word_emb  = (const float*)d_in[4];
    const float* c_Wih     = (const float*)d_in[5];
    const float* c_Whh     = (const float*)d_in[6];
    const float* c_bih     = (const float*)d_in[7];
    const float* c_bhh     = (const float*)d_in[8];
    const float* w_Wih     = (const float*)d_in[9];
    const float* w_Whh     = (const float*)d_in[10];
    const float* w_bih     = (const float*)d_in[11];
    const float* w_bhh     = (const float*)d_in[12];
    const float* out_W     = (const float*)d_in[13];
    const float* out_b     = (const float*)d_in[14];
    float* out = (float*)d_out;

    prep_kernel<<<512, 256>>>(c_Wih, c_Whh, c_bih, c_bhh, w_bih, w_bhh, out_W);
    char_kernel<<<128, 256>>>(char_ids, char_lens, char_emb);
    pregemm_kernel<<<dim3(16, 32), 256>>>(w_Wih, word_ids, word_emb);
    word_kernel<<<WBLOCKS, 256>>>(w_Whh);
    out_kernel<<<256, 128>>>(out_b, out);
}